// round 1
// baseline (speedup 1.0000x reference)
#include <cuda_runtime.h>
#include <math.h>

#define NC 40
#define NB 1024

// ---------------- scratch (device globals; no allocation allowed) -----------
__device__ float  g_loss_sum[NC];
__device__ float  g_pos_sum[NC];
__device__ int    g_hist[NC * 2 * NB];
__device__ double g_acc;

// per-class params produced by pass2
__device__ float g_maj_lab[NC];
__device__ float g_min_lab[NC];
__device__ float g_w_maj[NC];
__device__ float g_w_min[NC];
__device__ float g_drate[NC];
__device__ float g_frac[NC];
__device__ int   g_hard[NC];
__device__ int   g_bin[NC];

// ---------------- helpers ----------------------------------------------------
__device__ __forceinline__ void bce_g(float x, float t, float& bce, float& g) {
    // logaddexp(0,x) - x*t  (numerically stable)
    float ax = fabsf(x);
    bce = fmaxf(x, 0.0f) + log1pf(expf(-ax)) - x * t;
    float p = 1.0f / (1.0f + expf(-x));
    g = fabsf(p - t);
}

__device__ __forceinline__ int g_to_bin(float g) {
    int b = (int)(g * (float)NB);
    return b > (NB - 1) ? (NB - 1) : b;
}

// ---------------- kernels -----------------------------------------------------
__global__ void zero_scratch() {
    int i = blockIdx.x * blockDim.x + threadIdx.x;
    int total = NC * 2 * NB;
    if (i < total) g_hist[i] = 0;
    if (i < NC) { g_loss_sum[i] = 0.0f; g_pos_sum[i] = 0.0f; }
    if (i == 0) g_acc = 0.0;
}

__global__ void pass1(const float* __restrict__ pred,
                      const float* __restrict__ target, int n) {
    __shared__ float s_loss[NC];
    __shared__ float s_pos[NC];
    if (threadIdx.x < NC) { s_loss[threadIdx.x] = 0.0f; s_pos[threadIdx.x] = 0.0f; }
    __syncthreads();

    int stride = gridDim.x * blockDim.x;
    for (int i = blockIdx.x * blockDim.x + threadIdx.x; i < n; i += stride) {
        float x = pred[i];
        float t = target[i];
        int c = i % NC;
        float bce, g;
        bce_g(x, t, bce, g);
        atomicAdd(&s_loss[c], bce);
        atomicAdd(&s_pos[c], t);
        int tl = (t != 0.0f) ? 1 : 0;
        atomicAdd(&g_hist[(c * 2 + tl) * NB + g_to_bin(g)], 1);
    }
    __syncthreads();
    if (threadIdx.x < NC) {
        atomicAdd(&g_loss_sum[threadIdx.x], s_loss[threadIdx.x]);
        atomicAdd(&g_pos_sum[threadIdx.x], s_pos[threadIdx.x]);
    }
}

__global__ void pass2(const float* __restrict__ hard_rand,
                      const float* __restrict__ pos_prop, float Bf) {
    __shared__ float s_ln[NC];
    int c = threadIdx.x;
    if (c < NC) s_ln[c] = log10f(1.0f + g_loss_sum[c]);
    __syncthreads();
    if (c >= NC) return;

    float mn = s_ln[0], mx = s_ln[0];
#pragma unroll
    for (int j = 1; j < NC; j++) { mn = fminf(mn, s_ln[j]); mx = fmaxf(mx, s_ln[j]); }

    float norm  = 5.0f - 10.0f * (s_ln[c] - mn) / (mx - mn);
    float drate = 1.0f / (1.0f + expf(-norm));   // max(.,0) is a no-op

    float pos = g_pos_sum[c];
    float neg = Bf - pos;
    float bal_pos = pos_prop[c] * Bf;
    float bal_neg = Bf - bal_pos;
    bool pos_gt = pos > bal_pos;
    bool neg_gt = neg > bal_neg;

    float balance_num = pos_gt ? bal_pos : (neg_gt ? bal_neg : 0.0f);
    float dnf         = pos_gt ? (pos - bal_pos) : (neg_gt ? (neg - bal_neg) : 0.0f);
    int   k           = (int)floorf(dnf);

    bool  hard    = hard_rand[c] > drate;
    float maj_lab = pos_gt ? 1.0f : 0.0f;
    float min_lab = neg_gt ? 1.0f : 0.0f;
    float maj_cnt = (maj_lab == 1.0f) ? pos : neg;
    float min_cnt = (min_lab == 1.0f) ? pos : neg;

    float w_maj = balance_num / fmaxf(maj_cnt, 1.0f);
    float w_min = (min_cnt > 0.0f) ? (Bf - balance_num) / fmaxf(min_cnt, 1.0f) : 1.0f;

    int   m    = -1;
    float frac = 0.0f;
    if (!hard && k > 0) {
        int tl = (maj_lab == 1.0f) ? 1 : 0;
        const int* h = &g_hist[(c * 2 + tl) * NB];
        int cum = 0;
        for (int b = 0; b < NB; b++) {
            int cb = h[b];
            if (cum + cb >= k) { m = b; frac = (float)(k - cum) / (float)cb; break; }
            cum += cb;
        }
    }

    g_maj_lab[c] = maj_lab;
    g_min_lab[c] = min_lab;
    g_w_maj[c]   = w_maj;
    g_w_min[c]   = w_min;
    g_drate[c]   = drate;
    g_hard[c]    = hard ? 1 : 0;
    g_bin[c]     = m;
    g_frac[c]    = frac;
}

__global__ void pass3(const float* __restrict__ pred,
                      const float* __restrict__ target,
                      const float* __restrict__ rand_mat, int n) {
    __shared__ float s_maj[NC], s_min[NC], s_wmaj[NC], s_wmin[NC];
    __shared__ float s_drate[NC], s_frac[NC];
    __shared__ int   s_hard[NC], s_bin[NC];
    if (threadIdx.x < NC) {
        int c = threadIdx.x;
        s_maj[c] = g_maj_lab[c];  s_min[c] = g_min_lab[c];
        s_wmaj[c] = g_w_maj[c];   s_wmin[c] = g_w_min[c];
        s_drate[c] = g_drate[c];  s_frac[c] = g_frac[c];
        s_hard[c] = g_hard[c];    s_bin[c] = g_bin[c];
    }
    __syncthreads();

    float local = 0.0f;
    int stride = gridDim.x * blockDim.x;
    for (int i = blockIdx.x * blockDim.x + threadIdx.x; i < n; i += stride) {
        float x = pred[i];
        float t = target[i];
        float r = rand_mat[i];
        int c = i % NC;
        float bce, g;
        bce_g(x, t, bce, g);

        bool is_maj = (t == s_maj[c]);
        float w;
        if (s_hard[c]) {
            w = is_maj ? s_wmaj[c] : 1.0f;
        } else {
            bool is_min = (t == s_min[c]);
            w = is_min ? s_wmin[c] : 1.0f;
            if (is_maj) {
                int bin = g_to_bin(g);
                int m = s_bin[c];
                if (bin < m)       w = 0.0f;
                else if (bin == m) w *= (1.0f - s_frac[c]);
            }
        }
        // hard-gradient band random drop: idxs = (g >= 0.8) & (g < 1+1e-6) [always < upper]
        if (g >= 0.8f && r > s_drate[c]) w = 0.0f;

        local += bce * w;
    }

    // block reduction
    __shared__ float red[256];
    red[threadIdx.x] = local;
    __syncthreads();
    for (int s = blockDim.x / 2; s > 0; s >>= 1) {
        if (threadIdx.x < s) red[threadIdx.x] += red[threadIdx.x + s];
        __syncthreads();
    }
    if (threadIdx.x == 0) atomicAdd(&g_acc, (double)red[0]);
}

__global__ void finalize(float* __restrict__ out, int n) {
    if (threadIdx.x == 0 && blockIdx.x == 0)
        out[0] = (float)(g_acc / (double)n);
}

// ---------------- launch ------------------------------------------------------
extern "C" void kernel_launch(void* const* d_in, const int* in_sizes, int n_in,
                              void* d_out, int out_size) {
    const float* pred      = (const float*)d_in[0];
    const float* target    = (const float*)d_in[1];
    const float* rand_mat  = (const float*)d_in[2];
    const float* hard_rand = (const float*)d_in[3];
    const float* pos_prop  = (const float*)d_in[4];
    float* out = (float*)d_out;

    int n = in_sizes[0];          // B*C
    float Bf = (float)(n / NC);   // B

    int zt = NC * 2 * NB;
    zero_scratch<<<(zt + 255) / 256, 256>>>();

    int blocks = 2048;
    pass1<<<blocks, 256>>>(pred, target, n);
    pass2<<<1, 64>>>(hard_rand, pos_prop, Bf);
    pass3<<<blocks, 256>>>(pred, target, rand_mat, n);
    finalize<<<1, 32>>>(out, n);
}

// round 3
// speedup vs baseline: 1.1345x; 1.1345x over previous
#include <cuda_runtime.h>
#include <math.h>

#define NC 40
#define NB 1024
#define BANDX 1.3862944f           // ln(4): g>=0.8 boundary in x
#define BINSCALE (1024.0f / 24.0f) // bins over x in [-12,12]

// ---------------- scratch (device globals) -----------------------------------
__device__ float  g_loss_sum[NC];
__device__ int    g_pos_sum[NC];
__device__ __align__(16) int g_hist[NC * NB];
__device__ double g_acc;

// per-class packed params
__device__ float g_c_fa[NC];     // +BINSCALE or -BINSCALE (g-ascending bin map)
__device__ float g_c_w1[NC];     // weight if t==1 (pre-drop)
__device__ float g_c_w0[NC];     // weight if t==0 (pre-drop)
__device__ float g_c_drate[NC];
__device__ float g_c_keep[NC];   // 1 - frac for boundary bin
__device__ int   g_c_m1[NC];     // drop-threshold bin if t==1 is majority else -1
__device__ int   g_c_m0[NC];
__device__ int   g_c_need[NC];
__device__ float g_c_majlab[NC];
__device__ int   g_c_k[NC];
__device__ int   g_c_majpos[NC];

// ---------------- kernels -----------------------------------------------------
__global__ void k_zero() {
    int i = blockIdx.x * blockDim.x + threadIdx.x;
    if (i < NC * NB) g_hist[i] = 0;
    if (i < NC) { g_loss_sum[i] = 0.0f; g_pos_sum[i] = 0; }
    if (i == 0) g_acc = 0.0;
}

// pass1a: per-class sum(bce), count(t==1). Register accumulation:
// grid*block*4 % 40 == 0 so each thread's 4 classes are fixed.
__global__ __launch_bounds__(256) void k_pass1a(const float4* __restrict__ pred,
                                                const float4* __restrict__ targ,
                                                int n4) {
    __shared__ float s_loss[NC];
    __shared__ int   s_pos[NC];
    int tid = threadIdx.x;
    if (tid < NC) { s_loss[tid] = 0.0f; s_pos[tid] = 0; }
    __syncthreads();

    int gt = blockIdx.x * blockDim.x + tid;
    int stride = gridDim.x * blockDim.x;
    int c0 = (gt * 4) % NC;

    float l[4] = {0.f, 0.f, 0.f, 0.f};
    int   p[4] = {0, 0, 0, 0};
    for (int i = gt; i < n4; i += stride) {
        float4 x = pred[i];
        float4 t = targ[i];
        float xs[4] = {x.x, x.y, x.z, x.w};
        float ts[4] = {t.x, t.y, t.z, t.w};
#pragma unroll
        for (int j = 0; j < 4; j++) {
            float xv = xs[j];
            bool  t1 = ts[j] != 0.0f;
            float ax = fabsf(xv);
            float e  = __expf(-ax);
            float L  = __logf(1.0f + e);
            bool mism = (xv >= 0.0f) != t1;
            l[j] += mism ? (L + ax) : L;
            p[j] += t1 ? 1 : 0;
        }
    }
#pragma unroll
    for (int j = 0; j < 4; j++) {
        atomicAdd(&s_loss[c0 + j], l[j]);
        atomicAdd(&s_pos[c0 + j], p[j]);
    }
    __syncthreads();
    if (tid < NC) {
        atomicAdd(&g_loss_sum[tid], s_loss[tid]);
        atomicAdd(&g_pos_sum[tid], s_pos[tid]);
    }
}

// pass2a: per-class scalars -> packed params
__global__ void k_pass2a(const float* __restrict__ hard_rand,
                         const float* __restrict__ pos_prop, float Bf) {
    __shared__ float s_ln[NC];
    int c = threadIdx.x;
    if (c < NC) s_ln[c] = log10f(1.0f + g_loss_sum[c]);
    __syncthreads();
    if (c >= NC) return;

    float mn = s_ln[0], mx = s_ln[0];
#pragma unroll
    for (int j = 1; j < NC; j++) { mn = fminf(mn, s_ln[j]); mx = fmaxf(mx, s_ln[j]); }

    float norm  = 5.0f - 10.0f * (s_ln[c] - mn) / (mx - mn);
    float drate = 1.0f / (1.0f + expf(-norm));

    float pos = (float)g_pos_sum[c];
    float neg = Bf - pos;
    float bal_pos = pos_prop[c] * Bf;
    float bal_neg = Bf - bal_pos;
    bool pos_gt = pos > bal_pos;
    bool neg_gt = neg > bal_neg;

    float balance = pos_gt ? bal_pos : (neg_gt ? bal_neg : 0.0f);
    float dnf     = pos_gt ? (pos - bal_pos) : (neg_gt ? (neg - bal_neg) : 0.0f);
    int   k       = (int)floorf(dnf);

    bool  hard    = hard_rand[c] > drate;
    float maj_lab = pos_gt ? 1.0f : 0.0f;
    float min_lab = neg_gt ? 1.0f : 0.0f;
    float maj_cnt = (maj_lab == 1.0f) ? pos : neg;
    float min_cnt = (min_lab == 1.0f) ? pos : neg;

    float w_maj    = balance / fmaxf(maj_cnt, 1.0f);
    float wmin_eff = (min_cnt > 0.0f) ? (Bf - balance) / fmaxf(min_cnt, 1.0f) : 1.0f;

    int majpos = (maj_lab == 1.0f) ? 1 : 0;
    bool need = (!hard) && (k > 0);

    g_c_fa[c]    = majpos ? -BINSCALE : BINSCALE;
    g_c_w1[c]    = hard ? (majpos ? w_maj : 1.0f) : ((min_lab == 1.0f) ? wmin_eff : 1.0f);
    g_c_w0[c]    = hard ? (majpos ? 1.0f : w_maj) : ((min_lab == 1.0f) ? 1.0f : wmin_eff);
    g_c_drate[c] = drate;
    g_c_keep[c]  = 1.0f;
    g_c_m1[c]    = -1;
    g_c_m0[c]    = -1;
    g_c_need[c]  = need ? 1 : 0;
    g_c_majlab[c] = maj_lab;
    g_c_k[c]     = k;
    g_c_majpos[c] = majpos;
}

// pass1b: histogram of g-ordered x-bins, only for easy classes' majority elements
__global__ __launch_bounds__(256) void k_pass1b(const float4* __restrict__ pred,
                                                const float4* __restrict__ targ,
                                                int n4) {
    int gt = blockIdx.x * blockDim.x + threadIdx.x;
    int stride = gridDim.x * blockDim.x;
    int c0 = (gt * 4) % NC;

    float majl[4], fa[4];
    int nd[4];
#pragma unroll
    for (int j = 0; j < 4; j++) {
        majl[j] = g_c_majlab[c0 + j];
        fa[j]   = g_c_fa[c0 + j];
        nd[j]   = g_c_need[c0 + j];
    }
    int anyneed = nd[0] | nd[1] | nd[2] | nd[3];
    if (!anyneed) return;

    for (int i = gt; i < n4; i += stride) {
        float4 x = pred[i];
        float4 t = targ[i];
        float xs[4] = {x.x, x.y, x.z, x.w};
        float ts[4] = {t.x, t.y, t.z, t.w};
#pragma unroll
        for (int j = 0; j < 4; j++) {
            if (nd[j] && ts[j] == majl[j]) {
                int b = (int)fmaf(xs[j], fa[j], 512.0f);
                b = min(max(b, 0), NB - 1);
                atomicAdd(&g_hist[(c0 + j) * NB + b], 1);
            }
        }
    }
}

// pass2b: per-class scan -> boundary bin m + keep fraction.
// 1 block, 256 threads = 8 warps; each warp strides over classes.
__global__ __launch_bounds__(256) void k_pass2b() {
    int warp = threadIdx.x >> 5;
    int lane = threadIdx.x & 31;
    for (int c = warp; c < NC; c += 8) {
        if (!g_c_need[c]) continue;
        int k = g_c_k[c];
        const int4* hv = (const int4*)&g_hist[c * NB];
        int v[32];
        int sum = 0;
#pragma unroll
        for (int j = 0; j < 8; j++) {
            int4 q = hv[lane * 8 + j];
            v[j * 4 + 0] = q.x; v[j * 4 + 1] = q.y;
            v[j * 4 + 2] = q.z; v[j * 4 + 3] = q.w;
            sum += q.x + q.y + q.z + q.w;
        }
        int incl = sum;
#pragma unroll
        for (int o = 1; o < 32; o <<= 1) {
            int u = __shfl_up_sync(0xffffffffu, incl, o);
            if (lane >= o) incl += u;
        }
        unsigned ball = __ballot_sync(0xffffffffu, incl >= k);
        int sel = __ffs(ball) - 1;
        if (lane == sel) {
            int cum = incl - sum;
            int m = -1;
            float keep = 1.0f;
#pragma unroll
            for (int j = 0; j < 32; j++) {
                int cb = v[j];
                if (m < 0 && cum + cb >= k) {
                    m = lane * 32 + j;
                    keep = 1.0f - (float)(k - cum) / (float)cb;
                }
                cum += cb;
            }
            g_c_keep[c] = keep;
            if (g_c_majpos[c]) g_c_m1[c] = m; else g_c_m0[c] = m;
        }
    }
}

// pass3: weighted sum
__global__ __launch_bounds__(256) void k_pass3(const float4* __restrict__ pred,
                                               const float4* __restrict__ targ,
                                               const float4* __restrict__ rm,
                                               int n4) {
    int tid = threadIdx.x;
    int gt = blockIdx.x * blockDim.x + tid;
    int stride = gridDim.x * blockDim.x;
    int c0 = (gt * 4) % NC;

    float fa[4], w1[4], w0[4], dr[4], kp[4];
    int m1[4], m0[4];
#pragma unroll
    for (int j = 0; j < 4; j++) {
        int c = c0 + j;
        fa[j] = g_c_fa[c];  w1[j] = g_c_w1[c];  w0[j] = g_c_w0[c];
        dr[j] = g_c_drate[c]; kp[j] = g_c_keep[c];
        m1[j] = g_c_m1[c];  m0[j] = g_c_m0[c];
    }

    float local = 0.0f;
    for (int i = gt; i < n4; i += stride) {
        float4 x = pred[i];
        float4 t = targ[i];
        float4 r = rm[i];
        float xs[4] = {x.x, x.y, x.z, x.w};
        float ts[4] = {t.x, t.y, t.z, t.w};
        float rs[4] = {r.x, r.y, r.z, r.w};
#pragma unroll
        for (int j = 0; j < 4; j++) {
            float xv = xs[j];
            bool  t1 = ts[j] != 0.0f;
            float ax = fabsf(xv);
            float e  = __expf(-ax);
            float L  = __logf(1.0f + e);
            bool mism = (xv >= 0.0f) != t1;
            float bce = mism ? (L + ax) : L;

            float w = t1 ? w1[j] : w0[j];
            int   m = t1 ? m1[j] : m0[j];
            if (m >= 0) {
                int b = (int)fmaf(xv, fa[j], 512.0f);
                b = min(max(b, 0), NB - 1);
                if (b < m)       w = 0.0f;
                else if (b == m) w *= kp[j];
            }
            if (mism && ax >= BANDX && rs[j] > dr[j]) w = 0.0f;
            local = fmaf(bce, w, local);
        }
    }

    // warp reduce -> block reduce -> double atomic
#pragma unroll
    for (int o = 16; o > 0; o >>= 1)
        local += __shfl_down_sync(0xffffffffu, local, o);
    __shared__ float s_red[8];
    int wid = tid >> 5, lane = tid & 31;
    if (lane == 0) s_red[wid] = local;
    __syncthreads();
    if (wid == 0) {
        float v = (lane < (blockDim.x >> 5)) ? s_red[lane] : 0.0f;
#pragma unroll
        for (int o = 4; o > 0; o >>= 1)
            v += __shfl_down_sync(0xffffffffu, v, o);
        if (lane == 0) atomicAdd(&g_acc, (double)v);
    }
}

__global__ void k_fin(float* __restrict__ out, int n) {
    if (threadIdx.x == 0 && blockIdx.x == 0)
        out[0] = (float)(g_acc / (double)n);
}

// ---------------- launch ------------------------------------------------------
extern "C" void kernel_launch(void* const* d_in, const int* in_sizes, int n_in,
                              void* d_out, int out_size) {
    const float4* pred     = (const float4*)d_in[0];
    const float4* targ     = (const float4*)d_in[1];
    const float4* rm       = (const float4*)d_in[2];
    const float*  hard_rnd = (const float*)d_in[3];
    const float*  pos_prop = (const float*)d_in[4];
    float* out = (float*)d_out;

    int n  = in_sizes[0];           // B*C (divisible by 4)
    int n4 = n / 4;
    float Bf = (float)(n / NC);

    // grid*256*4 % 40 == 0  <=>  grid % 5 == 0 (fixed-class trick)
    const int G = 1180;             // ~8 blocks/SM, one wave

    k_zero<<<(NC * NB + 255) / 256, 256>>>();
    k_pass1a<<<G, 256>>>(pred, targ, n4);
    k_pass2a<<<1, 64>>>(hard_rnd, pos_prop, Bf);
    k_pass1b<<<G, 256>>>(pred, targ, n4);
    k_pass2b<<<1, 256>>>();
    k_pass3<<<G, 256>>>(pred, targ, rm, n4);
    k_fin<<<1, 32>>>(out, n);
}

// round 4
// speedup vs baseline: 1.1429x; 1.0074x over previous
#include <cuda_runtime.h>
#include <math.h>

#define NC 40
#define NB 256                    // histogram bins over x in [-12,12]
#define NWD (NB/2)                // packed u32 words per class-label = 128
#define NCL (NC*2)                // class-label pairs = 80
#define WORDS (NCL*NWD)           // 10240 words per block histogram
#define G1 590                    // pass1 grid (%5==0 for fixed-class trick)
#define G3 1180                   // pass3 grid (%5==0)
#define BANDX 1.3862944f          // ln(4): g>=0.8 boundary in |x| (mismatch side)
#define BSC (256.0f/24.0f)        // x -> bin scale

// ---------------- scratch (device globals) -----------------------------------
__device__ float    g_loss_sum[NC];
__device__ unsigned g_pos_sum[NC];
__device__ unsigned g_part[G1 * WORDS];   // per-block packed histograms (~24 MB, bss)
__device__ unsigned g_hist2[NCL * NB];    // reduced counts (written only where needed)
__device__ double   g_acc;

// per-class packed params
__device__ float g_c_w1[NC];     // weight if t==1 (pre-drop)
__device__ float g_c_w0[NC];     // weight if t==0 (pre-drop)
__device__ float g_c_drate[NC];
__device__ float g_c_keep[NC];   // keep fraction for boundary bin
__device__ int   g_c_m1[NC];     // threshold bin when majority label==1 (else -1)
__device__ int   g_c_m0[NC];     // threshold bin when majority label==0 (else -1)
__device__ int   g_c_need[NC];
__device__ int   g_c_majpos[NC];
__device__ int   g_c_k[NC];

// ---------------- kernels -----------------------------------------------------
__global__ void k_zero() {
    int i = threadIdx.x;
    if (i < NC) { g_loss_sum[i] = 0.0f; g_pos_sum[i] = 0u; }
    if (i == 0) g_acc = 0.0;
}

// fused pass1: per-class sum(bce), count(t==1), and per-label x-bin histogram
// privatized in smem (16-bit packed), dumped per block (no global atomics).
__global__ __launch_bounds__(256) void k_pass1(const float4* __restrict__ pred,
                                               const float4* __restrict__ targ,
                                               int n4) {
    __shared__ unsigned s_h[WORDS];          // 40 KB
    __shared__ float    s_loss[NC];
    __shared__ unsigned s_pos[NC];
    int tid = threadIdx.x;
    for (int i = tid; i < WORDS; i += 256) s_h[i] = 0u;
    if (tid < NC) { s_loss[tid] = 0.0f; s_pos[tid] = 0u; }
    __syncthreads();

    int gt = blockIdx.x * 256 + tid;
    int stride = gridDim.x * 256;
    int c0 = (gt * 4) % NC;                  // fixed per thread (stride%40==0)

    float    l[4] = {0.f, 0.f, 0.f, 0.f};
    unsigned p[4] = {0u, 0u, 0u, 0u};
    for (int i = gt; i < n4; i += stride) {
        float4 x = pred[i];
        float4 t = targ[i];
        float xs[4] = {x.x, x.y, x.z, x.w};
        float ts[4] = {t.x, t.y, t.z, t.w};
#pragma unroll
        for (int j = 0; j < 4; j++) {
            float xv = xs[j];
            int   t1 = (ts[j] != 0.0f) ? 1 : 0;
            float ax = fabsf(xv);
            float L  = __logf(1.0f + __expf(-ax));
            bool mism = (xv >= 0.0f) != (t1 != 0);
            l[j] += mism ? (L + ax) : L;
            p[j] += (unsigned)t1;
            int b = (int)fmaf(xv, BSC, 128.0f);
            b = min(max(b, 0), NB - 1);
            int w = ((c0 + j) * 2 + t1) * NWD + (b >> 1);
            atomicAdd(&s_h[w], 1u << ((b & 1) << 4));
        }
    }
#pragma unroll
    for (int j = 0; j < 4; j++) {
        atomicAdd(&s_loss[c0 + j], l[j]);
        atomicAdd(&s_pos[c0 + j], p[j]);
    }
    __syncthreads();
    unsigned* dst = &g_part[blockIdx.x * WORDS];
    for (int i = tid; i < WORDS; i += 256) dst[i] = s_h[i];
    if (tid < NC) {
        atomicAdd(&g_loss_sum[tid], s_loss[tid]);
        atomicAdd(&g_pos_sum[tid], s_pos[tid]);
    }
}

// pass2a: per-class scalars -> packed params (also decides which hist columns matter)
__global__ void k_pass2a(const float* __restrict__ hard_rand,
                         const float* __restrict__ pos_prop, float Bf) {
    __shared__ float s_ln[NC];
    int c = threadIdx.x;
    if (c < NC) s_ln[c] = log10f(1.0f + g_loss_sum[c]);
    __syncthreads();
    if (c >= NC) return;

    float mn = s_ln[0], mx = s_ln[0];
#pragma unroll
    for (int j = 1; j < NC; j++) { mn = fminf(mn, s_ln[j]); mx = fmaxf(mx, s_ln[j]); }

    float norm  = 5.0f - 10.0f * (s_ln[c] - mn) / (mx - mn);
    float drate = 1.0f / (1.0f + expf(-norm));

    float pos = (float)g_pos_sum[c];
    float neg = Bf - pos;
    float bal_pos = pos_prop[c] * Bf;
    float bal_neg = Bf - bal_pos;
    bool pos_gt = pos > bal_pos;
    bool neg_gt = neg > bal_neg;

    float balance = pos_gt ? bal_pos : (neg_gt ? bal_neg : 0.0f);
    float dnf     = pos_gt ? (pos - bal_pos) : (neg_gt ? (neg - bal_neg) : 0.0f);
    int   k       = (int)floorf(dnf);

    bool  hard    = hard_rand[c] > drate;
    float maj_lab = pos_gt ? 1.0f : 0.0f;
    float min_lab = neg_gt ? 1.0f : 0.0f;
    float maj_cnt = (maj_lab == 1.0f) ? pos : neg;
    float min_cnt = (min_lab == 1.0f) ? pos : neg;

    float w_maj    = balance / fmaxf(maj_cnt, 1.0f);
    float wmin_eff = (min_cnt > 0.0f) ? (Bf - balance) / fmaxf(min_cnt, 1.0f) : 1.0f;

    int majpos = (maj_lab == 1.0f) ? 1 : 0;
    bool need = (!hard) && (k > 0);

    g_c_w1[c]     = hard ? (majpos ? w_maj : 1.0f) : ((min_lab == 1.0f) ? wmin_eff : 1.0f);
    g_c_w0[c]     = hard ? (majpos ? 1.0f : w_maj) : ((min_lab == 1.0f) ? 1.0f : wmin_eff);
    g_c_drate[c]  = drate;
    g_c_keep[c]   = 1.0f;
    g_c_m1[c]     = -1;
    g_c_m0[c]     = -1;
    g_c_need[c]   = need ? 1 : 0;
    g_c_majpos[c] = majpos;
    g_c_k[c]      = k;
}

// reduce per-block histograms -> g_hist2, only for needed (class, majority-label) columns
__global__ __launch_bounds__(256) void k_reduce() {
    int w = blockIdx.x * 256 + threadIdx.x;       // 0..WORDS-1
    int cl = w >> 7;                              // class-label index (NWD=128)
    int c = cl >> 1, lab = cl & 1;
    if (!g_c_need[c] || lab != g_c_majpos[c]) return;
    unsigned lo = 0, hi = 0;
#pragma unroll 4
    for (int b = 0; b < G1; b++) {
        unsigned v = g_part[b * WORDS + w];
        lo += v & 0xffffu;
        hi += v >> 16;
    }
    int wb = w & (NWD - 1);
    g_hist2[cl * NB + wb * 2]     = lo;
    g_hist2[cl * NB + wb * 2 + 1] = hi;
}

// pass2b: per-class g-ordered cumulative scan -> boundary bin m + keep fraction.
__global__ __launch_bounds__(256) void k_pass2b() {
    int warp = threadIdx.x >> 5;
    int lane = threadIdx.x & 31;
    for (int c = warp; c < NC; c += 8) {
        if (!g_c_need[c]) continue;
        int k  = g_c_k[c];
        int mp = g_c_majpos[c];
        const unsigned* h = &g_hist2[(c * 2 + mp) * NB];
        int v[8];
        int sum = 0;
#pragma unroll
        for (int j = 0; j < 8; j++) {
            int gi  = lane * 8 + j;                    // g-ascending index
            int bin = mp ? (NB - 1 - gi) : gi;         // majority=1 -> g desc in x
            v[j] = (int)h[bin];
            sum += v[j];
        }
        int incl = sum;
#pragma unroll
        for (int o = 1; o < 32; o <<= 1) {
            int u = __shfl_up_sync(0xffffffffu, incl, o);
            if (lane >= o) incl += u;
        }
        unsigned ball = __ballot_sync(0xffffffffu, incl >= k);
        int sel = __ffs(ball) - 1;
        if (lane == sel) {
            int cum = incl - sum;
            int m = -1;
            float keep = 1.0f;
#pragma unroll
            for (int j = 0; j < 8; j++) {
                int cb = v[j];
                if (m < 0 && cum + cb >= k) {
                    int gi = lane * 8 + j;
                    m = mp ? (NB - 1 - gi) : gi;
                    keep = 1.0f - (float)(k - cum) / (float)cb;
                }
                cum += cb;
            }
            g_c_keep[c] = keep;
            if (mp) g_c_m1[c] = m; else g_c_m0[c] = m;
        }
    }
}

// pass3: weighted sum
__global__ __launch_bounds__(256) void k_pass3(const float4* __restrict__ pred,
                                               const float4* __restrict__ targ,
                                               const float4* __restrict__ rm,
                                               int n4) {
    int tid = threadIdx.x;
    int gt = blockIdx.x * 256 + tid;
    int stride = gridDim.x * 256;
    int c0 = (gt * 4) % NC;

    float w1[4], w0[4], dr[4], kp[4];
    int m1[4], m0[4];
#pragma unroll
    for (int j = 0; j < 4; j++) {
        int c = c0 + j;
        w1[j] = g_c_w1[c];  w0[j] = g_c_w0[c];
        dr[j] = g_c_drate[c]; kp[j] = g_c_keep[c];
        m1[j] = g_c_m1[c];  m0[j] = g_c_m0[c];
    }

    float local = 0.0f;
    for (int i = gt; i < n4; i += stride) {
        float4 x = pred[i];
        float4 t = targ[i];
        float4 r = rm[i];
        float xs[4] = {x.x, x.y, x.z, x.w};
        float ts[4] = {t.x, t.y, t.z, t.w};
        float rs[4] = {r.x, r.y, r.z, r.w};
#pragma unroll
        for (int j = 0; j < 4; j++) {
            float xv = xs[j];
            bool  t1 = ts[j] != 0.0f;
            float ax = fabsf(xv);
            float L  = __logf(1.0f + __expf(-ax));
            bool mism = (xv >= 0.0f) != t1;
            float bce = mism ? (L + ax) : L;

            int b = (int)fmaf(xv, BSC, 128.0f);
            b = min(max(b, 0), NB - 1);

            float w = t1 ? w1[j] : w0[j];
            int   m = t1 ? m1[j] : m0[j];
            if (m >= 0) {
                // majority-label==1: easiest = largest x (drop b>m);
                // majority-label==0: easiest = smallest x (drop b<m)
                bool drop = t1 ? (b > m) : (b < m);
                if (drop)        w = 0.0f;
                else if (b == m) w *= kp[j];
            }
            if (mism && ax >= BANDX && rs[j] > dr[j]) w = 0.0f;
            local = fmaf(bce, w, local);
        }
    }

    // warp reduce -> block reduce -> double atomic
#pragma unroll
    for (int o = 16; o > 0; o >>= 1)
        local += __shfl_down_sync(0xffffffffu, local, o);
    __shared__ float s_red[8];
    int wid = tid >> 5, lane = tid & 31;
    if (lane == 0) s_red[wid] = local;
    __syncthreads();
    if (wid == 0) {
        float v = (lane < 8) ? s_red[lane] : 0.0f;
#pragma unroll
        for (int o = 4; o > 0; o >>= 1)
            v += __shfl_down_sync(0xffffffffu, v, o);
        if (lane == 0) atomicAdd(&g_acc, (double)v);
    }
}

__global__ void k_fin(float* __restrict__ out, int n) {
    if (threadIdx.x == 0 && blockIdx.x == 0)
        out[0] = (float)(g_acc / (double)n);
}

// ---------------- launch ------------------------------------------------------
extern "C" void kernel_launch(void* const* d_in, const int* in_sizes, int n_in,
                              void* d_out, int out_size) {
    const float4* pred     = (const float4*)d_in[0];
    const float4* targ     = (const float4*)d_in[1];
    const float4* rm       = (const float4*)d_in[2];
    const float*  hard_rnd = (const float*)d_in[3];
    const float*  pos_prop = (const float*)d_in[4];
    float* out = (float*)d_out;

    int n  = in_sizes[0];           // B*C (divisible by 4)
    int n4 = n / 4;
    float Bf = (float)(n / NC);

    k_zero<<<1, 64>>>();
    k_pass1<<<G1, 256>>>(pred, targ, n4);
    k_pass2a<<<1, 64>>>(hard_rnd, pos_prop, Bf);
    k_reduce<<<WORDS / 256, 256>>>();
    k_pass2b<<<1, 256>>>();
    k_pass3<<<G3, 256>>>(pred, targ, rm, n4);
    k_fin<<<1, 32>>>(out, n);
}

// round 5
// speedup vs baseline: 2.0419x; 1.7866x over previous
#include <cuda_runtime.h>
#include <math.h>

#define NC 40
#define NB 256                    // histogram bins over x in [-12,12]
#define NWD (NB/2)                // packed u32 words per class-label = 128
#define NCL (NC*2)                // class-label pairs = 80
#define WORDS (NCL*NWD)           // 10240 words per block histogram
#define G1 145                    // pass1 grid: 1 block/SM, %5==0 (fixed-class trick)
#define T1 1024                   // pass1 block size
#define G3 1180                   // pass3 grid (%5==0)
#define BANDX 1.3862944f          // ln(4): g>=0.8 boundary in |x| (mismatch side)
#define BSC (256.0f/24.0f)        // x -> bin scale

// ---------------- scratch (device globals) -----------------------------------
__device__ float    g_loss_sum[NC];
__device__ unsigned g_pos_sum[NC];
__device__ unsigned g_part[G1 * WORDS];   // per-block packed histograms (~6 MB)
__device__ unsigned g_hist2[NCL * NB];    // reduced counts (written only where needed)
__device__ double   g_acc;

// per-class packed params
__device__ float g_c_w1[NC];     // weight if t==1 (pre-drop)
__device__ float g_c_w0[NC];     // weight if t==0 (pre-drop)
__device__ float g_c_drate[NC];
__device__ float g_c_keep[NC];   // keep fraction for boundary bin
__device__ int   g_c_m1[NC];     // threshold bin when majority label==1 (else -1)
__device__ int   g_c_m0[NC];     // threshold bin when majority label==0 (else -1)
__device__ int   g_c_need[NC];
__device__ int   g_c_majpos[NC];
__device__ int   g_c_k[NC];

// ---------------- kernels -----------------------------------------------------
__global__ void k_zero() {
    int i = threadIdx.x;
    if (i < NC) { g_loss_sum[i] = 0.0f; g_pos_sum[i] = 0u; }
    if (i == 0) g_acc = 0.0;
}

// fused pass1: per-class sum(bce), count(t==1), and per-label x-bin histogram
// privatized in smem (16-bit packed), dumped per block (no global atomics).
__global__ __launch_bounds__(T1) void k_pass1(const float4* __restrict__ pred,
                                              const float4* __restrict__ targ,
                                              int n4) {
    __shared__ unsigned s_h[WORDS];          // 40 KB
    __shared__ float    s_loss[NC];
    __shared__ unsigned s_pos[NC];
    int tid = threadIdx.x;
    for (int i = tid; i < WORDS; i += T1) s_h[i] = 0u;
    if (tid < NC) { s_loss[tid] = 0.0f; s_pos[tid] = 0u; }
    __syncthreads();

    int gt = blockIdx.x * T1 + tid;
    int stride = G1 * T1;
    int c0 = (gt * 4) % NC;                  // fixed per thread (stride*4 % 40 == 0)

    float    l[4] = {0.f, 0.f, 0.f, 0.f};
    unsigned p[4] = {0u, 0u, 0u, 0u};
    for (int i = gt; i < n4; i += stride) {
        float4 x = pred[i];
        float4 t = targ[i];
        float xs[4] = {x.x, x.y, x.z, x.w};
        float ts[4] = {t.x, t.y, t.z, t.w};
#pragma unroll
        for (int j = 0; j < 4; j++) {
            float xv = xs[j];
            int   t1 = (ts[j] != 0.0f) ? 1 : 0;
            float ax = fabsf(xv);
            float L  = __logf(1.0f + __expf(-ax));
            bool mism = (xv >= 0.0f) != (t1 != 0);
            l[j] += mism ? (L + ax) : L;
            p[j] += (unsigned)t1;
            int b = (int)fmaf(xv, BSC, 128.0f);
            b = min(max(b, 0), NB - 1);
            int w = ((c0 + j) * 2 + t1) * NWD + (b >> 1);
            atomicAdd(&s_h[w], 1u << ((b & 1) << 4));
        }
    }
#pragma unroll
    for (int j = 0; j < 4; j++) {
        atomicAdd(&s_loss[c0 + j], l[j]);
        atomicAdd(&s_pos[c0 + j], p[j]);
    }
    __syncthreads();
    unsigned* dst = &g_part[blockIdx.x * WORDS];
    for (int i = tid; i < WORDS; i += T1) dst[i] = s_h[i];
    if (tid < NC) {
        atomicAdd(&g_loss_sum[tid], s_loss[tid]);
        atomicAdd(&g_pos_sum[tid], s_pos[tid]);
    }
}

// pass2a: per-class scalars -> packed params (also decides which hist columns matter)
__global__ void k_pass2a(const float* __restrict__ hard_rand,
                         const float* __restrict__ pos_prop, float Bf) {
    __shared__ float s_ln[NC];
    int c = threadIdx.x;
    if (c < NC) s_ln[c] = log10f(1.0f + g_loss_sum[c]);
    __syncthreads();
    if (c >= NC) return;

    float mn = s_ln[0], mx = s_ln[0];
#pragma unroll
    for (int j = 1; j < NC; j++) { mn = fminf(mn, s_ln[j]); mx = fmaxf(mx, s_ln[j]); }

    float norm  = 5.0f - 10.0f * (s_ln[c] - mn) / (mx - mn);
    float drate = 1.0f / (1.0f + expf(-norm));

    float pos = (float)g_pos_sum[c];
    float neg = Bf - pos;
    float bal_pos = pos_prop[c] * Bf;
    float bal_neg = Bf - bal_pos;
    bool pos_gt = pos > bal_pos;
    bool neg_gt = neg > bal_neg;

    float balance = pos_gt ? bal_pos : (neg_gt ? bal_neg : 0.0f);
    float dnf     = pos_gt ? (pos - bal_pos) : (neg_gt ? (neg - bal_neg) : 0.0f);
    int   k       = (int)floorf(dnf);

    bool  hard    = hard_rand[c] > drate;
    float maj_lab = pos_gt ? 1.0f : 0.0f;
    float min_lab = neg_gt ? 1.0f : 0.0f;
    float maj_cnt = (maj_lab == 1.0f) ? pos : neg;
    float min_cnt = (min_lab == 1.0f) ? pos : neg;

    float w_maj    = balance / fmaxf(maj_cnt, 1.0f);
    float wmin_eff = (min_cnt > 0.0f) ? (Bf - balance) / fmaxf(min_cnt, 1.0f) : 1.0f;

    int majpos = (maj_lab == 1.0f) ? 1 : 0;
    bool need = (!hard) && (k > 0);

    g_c_w1[c]     = hard ? (majpos ? w_maj : 1.0f) : ((min_lab == 1.0f) ? wmin_eff : 1.0f);
    g_c_w0[c]     = hard ? (majpos ? 1.0f : w_maj) : ((min_lab == 1.0f) ? 1.0f : wmin_eff);
    g_c_drate[c]  = drate;
    g_c_keep[c]   = 1.0f;
    g_c_m1[c]     = -1;
    g_c_m0[c]     = -1;
    g_c_need[c]   = need ? 1 : 0;
    g_c_majpos[c] = majpos;
    g_c_k[c]      = k;
}

// reduce per-block histograms -> g_hist2, only for needed (class, majority-label)
// columns. One thread per word, deep unroll for MLP (depth G1=145).
__global__ __launch_bounds__(256) void k_reduce() {
    int w = blockIdx.x * 256 + threadIdx.x;       // 0..WORDS-1
    int cl = w >> 7;                              // class-label index (NWD=128)
    int c = cl >> 1, lab = cl & 1;
    if (!g_c_need[c] || lab != g_c_majpos[c]) return;
    unsigned lo = 0, hi = 0;
    int b = 0;
#pragma unroll
    for (; b + 16 <= G1; b += 16) {
        unsigned v[16];
#pragma unroll
        for (int u = 0; u < 16; u++) v[u] = g_part[(b + u) * WORDS + w];
#pragma unroll
        for (int u = 0; u < 16; u++) { lo += v[u] & 0xffffu; hi += v[u] >> 16; }
    }
    for (; b < G1; b++) {
        unsigned v = g_part[b * WORDS + w];
        lo += v & 0xffffu;
        hi += v >> 16;
    }
    int wb = w & (NWD - 1);
    g_hist2[cl * NB + wb * 2]     = lo;
    g_hist2[cl * NB + wb * 2 + 1] = hi;
}

// pass2b: per-class g-ordered cumulative scan -> boundary bin m + keep fraction.
__global__ __launch_bounds__(256) void k_pass2b() {
    int warp = threadIdx.x >> 5;
    int lane = threadIdx.x & 31;
    for (int c = warp; c < NC; c += 8) {
        if (!g_c_need[c]) continue;
        int k  = g_c_k[c];
        int mp = g_c_majpos[c];
        const unsigned* h = &g_hist2[(c * 2 + mp) * NB];
        int v[8];
        int sum = 0;
#pragma unroll
        for (int j = 0; j < 8; j++) {
            int gi  = lane * 8 + j;                    // g-ascending index
            int bin = mp ? (NB - 1 - gi) : gi;         // majority=1 -> g desc in x
            v[j] = (int)h[bin];
            sum += v[j];
        }
        int incl = sum;
#pragma unroll
        for (int o = 1; o < 32; o <<= 1) {
            int u = __shfl_up_sync(0xffffffffu, incl, o);
            if (lane >= o) incl += u;
        }
        unsigned ball = __ballot_sync(0xffffffffu, incl >= k);
        int sel = __ffs(ball) - 1;
        if (lane == sel) {
            int cum = incl - sum;
            int m = -1;
            float keep = 1.0f;
#pragma unroll
            for (int j = 0; j < 8; j++) {
                int cb = v[j];
                if (m < 0 && cum + cb >= k) {
                    int gi = lane * 8 + j;
                    m = mp ? (NB - 1 - gi) : gi;
                    keep = 1.0f - (float)(k - cum) / (float)cb;
                }
                cum += cb;
            }
            g_c_keep[c] = keep;
            if (mp) g_c_m1[c] = m; else g_c_m0[c] = m;
        }
    }
}

// pass3: weighted sum
__global__ __launch_bounds__(256) void k_pass3(const float4* __restrict__ pred,
                                               const float4* __restrict__ targ,
                                               const float4* __restrict__ rm,
                                               int n4) {
    int tid = threadIdx.x;
    int gt = blockIdx.x * 256 + tid;
    int stride = G3 * 256;
    int c0 = (gt * 4) % NC;

    float w1[4], w0[4], dr[4], kp[4];
    int m1[4], m0[4];
#pragma unroll
    for (int j = 0; j < 4; j++) {
        int c = c0 + j;
        w1[j] = g_c_w1[c];  w0[j] = g_c_w0[c];
        dr[j] = g_c_drate[c]; kp[j] = g_c_keep[c];
        m1[j] = g_c_m1[c];  m0[j] = g_c_m0[c];
    }

    float local = 0.0f;
    for (int i = gt; i < n4; i += stride) {
        float4 x = pred[i];
        float4 t = targ[i];
        float4 r = rm[i];
        float xs[4] = {x.x, x.y, x.z, x.w};
        float ts[4] = {t.x, t.y, t.z, t.w};
        float rs[4] = {r.x, r.y, r.z, r.w};
#pragma unroll
        for (int j = 0; j < 4; j++) {
            float xv = xs[j];
            bool  t1 = ts[j] != 0.0f;
            float ax = fabsf(xv);
            float L  = __logf(1.0f + __expf(-ax));
            bool mism = (xv >= 0.0f) != t1;
            float bce = mism ? (L + ax) : L;

            int b = (int)fmaf(xv, BSC, 128.0f);
            b = min(max(b, 0), NB - 1);

            float w = t1 ? w1[j] : w0[j];
            int   m = t1 ? m1[j] : m0[j];
            if (m >= 0) {
                // majority-label==1: easiest = largest x (drop b>m);
                // majority-label==0: easiest = smallest x (drop b<m)
                bool drop = t1 ? (b > m) : (b < m);
                if (drop)        w = 0.0f;
                else if (b == m) w *= kp[j];
            }
            if (mism && ax >= BANDX && rs[j] > dr[j]) w = 0.0f;
            local = fmaf(bce, w, local);
        }
    }

    // warp reduce -> block reduce -> double atomic
#pragma unroll
    for (int o = 16; o > 0; o >>= 1)
        local += __shfl_down_sync(0xffffffffu, local, o);
    __shared__ float s_red[8];
    int wid = tid >> 5, lane = tid & 31;
    if (lane == 0) s_red[wid] = local;
    __syncthreads();
    if (wid == 0) {
        float v = (lane < 8) ? s_red[lane] : 0.0f;
#pragma unroll
        for (int o = 4; o > 0; o >>= 1)
            v += __shfl_down_sync(0xffffffffu, v, o);
        if (lane == 0) atomicAdd(&g_acc, (double)v);
    }
}

__global__ void k_fin(float* __restrict__ out, int n) {
    if (threadIdx.x == 0 && blockIdx.x == 0)
        out[0] = (float)(g_acc / (double)n);
}

// ---------------- launch ------------------------------------------------------
extern "C" void kernel_launch(void* const* d_in, const int* in_sizes, int n_in,
                              void* d_out, int out_size) {
    const float4* pred     = (const float4*)d_in[0];
    const float4* targ     = (const float4*)d_in[1];
    const float4* rm       = (const float4*)d_in[2];
    const float*  hard_rnd = (const float*)d_in[3];
    const float*  pos_prop = (const float*)d_in[4];
    float* out = (float*)d_out;

    int n  = in_sizes[0];           // B*C (divisible by 4)
    int n4 = n / 4;
    float Bf = (float)(n / NC);

    k_zero<<<1, 64>>>();
    k_pass1<<<G1, T1>>>(pred, targ, n4);
    k_pass2a<<<1, 64>>>(hard_rnd, pos_prop, Bf);
    k_reduce<<<WORDS / 256, 256>>>();
    k_pass2b<<<1, 256>>>();
    k_pass3<<<G3, 256>>>(pred, targ, rm, n4);
    k_fin<<<1, 32>>>(out, n);
}

// round 6
// speedup vs baseline: 2.3597x; 1.1556x over previous
#include <cuda_runtime.h>
#include <math.h>

#define NC 40
#define NB 256                    // histogram bins over x in [-12,12]
#define NWD (NB/2)                // packed u32 words per class-label = 128
#define NCL (NC*2)                // class-label pairs = 80
#define WORDS (NCL*NWD)           // 10240 packed words
#define G1 145                    // pass1 grid: 1 block/SM, %5==0 (fixed-class trick)
#define T1 1024                   // pass1 block size
#define G3 1180                   // pass3 grid (%5==0)
#define BANDX 1.3862944f          // ln(4): g>=0.8 boundary in |x| (mismatch side)
#define BSC (256.0f/24.0f)        // x -> bin scale

// ---------------- scratch (device globals) -----------------------------------
__device__ float    g_loss_sum[NC];
__device__ unsigned g_pos_sum[NC];
__device__ unsigned g_hist[WORDS];       // packed 16-bit halves; max count/bin ~1.2K << 65536
__device__ double   g_acc;
__device__ unsigned g_done;

// per-class packed params
__device__ float g_c_w1[NC];     // weight if t==1 (pre-drop)
__device__ float g_c_w0[NC];     // weight if t==0 (pre-drop)
__device__ float g_c_drate[NC];
__device__ float g_c_keep[NC];   // keep fraction for boundary bin
__device__ int   g_c_m1[NC];     // threshold bin when majority label==1 (else -1)
__device__ int   g_c_m0[NC];     // threshold bin when majority label==0 (else -1)
__device__ int   g_c_need[NC];
__device__ int   g_c_majpos[NC];
__device__ int   g_c_k[NC];

// ---------------- kernels -----------------------------------------------------
__global__ void k_zero() {
    int i = blockIdx.x * 256 + threadIdx.x;
    if (i < WORDS) g_hist[i] = 0u;
    if (i < NC) { g_loss_sum[i] = 0.0f; g_pos_sum[i] = 0u; }
    if (i == 0) { g_acc = 0.0; g_done = 0u; }
}

// fused pass1: per-class sum(bce), count(t==1), per-label x-bin histogram
// privatized in smem (16-bit packed); flushed with spread global atomics.
__global__ __launch_bounds__(T1) void k_pass1(const float4* __restrict__ pred,
                                              const float4* __restrict__ targ,
                                              int n4) {
    __shared__ unsigned s_h[WORDS];          // 40 KB
    __shared__ float    s_loss[NC];
    __shared__ unsigned s_pos[NC];
    int tid = threadIdx.x;
    for (int i = tid; i < WORDS; i += T1) s_h[i] = 0u;
    if (tid < NC) { s_loss[tid] = 0.0f; s_pos[tid] = 0u; }
    __syncthreads();

    int gt = blockIdx.x * T1 + tid;
    int stride = G1 * T1;
    int c0 = (gt * 4) % NC;                  // fixed per thread (stride*4 % 40 == 0)

    float    l[4] = {0.f, 0.f, 0.f, 0.f};
    unsigned p[4] = {0u, 0u, 0u, 0u};
    for (int i = gt; i < n4; i += stride) {
        float4 x = pred[i];
        float4 t = targ[i];
        float xs[4] = {x.x, x.y, x.z, x.w};
        float ts[4] = {t.x, t.y, t.z, t.w};
#pragma unroll
        for (int j = 0; j < 4; j++) {
            float xv = xs[j];
            int   t1 = (ts[j] != 0.0f) ? 1 : 0;
            float ax = fabsf(xv);
            float L  = __logf(1.0f + __expf(-ax));
            bool mism = (xv >= 0.0f) != (t1 != 0);
            l[j] += mism ? (L + ax) : L;
            p[j] += (unsigned)t1;
            int b = (int)fmaf(xv, BSC, 128.0f);
            b = min(max(b, 0), NB - 1);
            int w = ((c0 + j) * 2 + t1) * NWD + (b >> 1);
            atomicAdd(&s_h[w], 1u << ((b & 1) << 4));
        }
    }
#pragma unroll
    for (int j = 0; j < 4; j++) {
        atomicAdd(&s_loss[c0 + j], l[j]);
        atomicAdd(&s_pos[c0 + j], p[j]);
    }
    __syncthreads();
    // flush: packed-word global atomics (halves can't carry; global max/bin ~1.2K)
    for (int i = tid; i < WORDS; i += T1) {
        unsigned v = s_h[i];
        if (v) atomicAdd(&g_hist[i], v);
    }
    if (tid < NC) {
        atomicAdd(&g_loss_sum[tid], s_loss[tid]);
        atomicAdd(&g_pos_sum[tid], s_pos[tid]);
    }
}

// fused pass2: per-class params, then g-ordered cumulative scan. 1 block.
__global__ __launch_bounds__(256) void k_pass2(const float* __restrict__ hard_rand,
                                               const float* __restrict__ pos_prop,
                                               float Bf) {
    __shared__ float s_ln[NC];
    int tid = threadIdx.x;
    if (tid < NC) s_ln[tid] = log10f(1.0f + g_loss_sum[tid]);
    __syncthreads();

    // ---- phase A: per-class params (threads 0..NC-1) ----
    if (tid < NC) {
        int c = tid;
        float mn = s_ln[0], mx = s_ln[0];
#pragma unroll
        for (int j = 1; j < NC; j++) { mn = fminf(mn, s_ln[j]); mx = fmaxf(mx, s_ln[j]); }

        float norm  = 5.0f - 10.0f * (s_ln[c] - mn) / (mx - mn);
        float drate = 1.0f / (1.0f + expf(-norm));

        float pos = (float)g_pos_sum[c];
        float neg = Bf - pos;
        float bal_pos = pos_prop[c] * Bf;
        float bal_neg = Bf - bal_pos;
        bool pos_gt = pos > bal_pos;
        bool neg_gt = neg > bal_neg;

        float balance = pos_gt ? bal_pos : (neg_gt ? bal_neg : 0.0f);
        float dnf     = pos_gt ? (pos - bal_pos) : (neg_gt ? (neg - bal_neg) : 0.0f);
        int   k       = (int)floorf(dnf);

        bool  hard    = hard_rand[c] > drate;
        float maj_lab = pos_gt ? 1.0f : 0.0f;
        float min_lab = neg_gt ? 1.0f : 0.0f;
        float maj_cnt = (maj_lab == 1.0f) ? pos : neg;
        float min_cnt = (min_lab == 1.0f) ? pos : neg;

        float w_maj    = balance / fmaxf(maj_cnt, 1.0f);
        float wmin_eff = (min_cnt > 0.0f) ? (Bf - balance) / fmaxf(min_cnt, 1.0f) : 1.0f;

        int majpos = (maj_lab == 1.0f) ? 1 : 0;
        bool need = (!hard) && (k > 0);

        g_c_w1[c]     = hard ? (majpos ? w_maj : 1.0f) : ((min_lab == 1.0f) ? wmin_eff : 1.0f);
        g_c_w0[c]     = hard ? (majpos ? 1.0f : w_maj) : ((min_lab == 1.0f) ? 1.0f : wmin_eff);
        g_c_drate[c]  = drate;
        g_c_keep[c]   = 1.0f;
        g_c_m1[c]     = -1;
        g_c_m0[c]     = -1;
        g_c_need[c]   = need ? 1 : 0;
        g_c_majpos[c] = majpos;
        g_c_k[c]      = k;
    }
    __syncthreads();   // also orders the global writes above for this block

    // ---- phase B: warp-per-class scan over packed histogram ----
    int warp = tid >> 5;
    int lane = tid & 31;
    for (int c = warp; c < NC; c += 8) {
        if (!g_c_need[c]) continue;
        int k  = g_c_k[c];
        int mp = g_c_majpos[c];
        const unsigned* hp = &g_hist[(c * 2 + mp) * NWD];
        int v[8];
        int sum = 0;
#pragma unroll
        for (int j = 0; j < 8; j++) {
            int gi  = lane * 8 + j;                    // g-ascending index
            int bin = mp ? (NB - 1 - gi) : gi;         // majority=1 -> g desc in x
            unsigned wv = hp[bin >> 1];
            v[j] = (int)((bin & 1) ? (wv >> 16) : (wv & 0xffffu));
            sum += v[j];
        }
        int incl = sum;
#pragma unroll
        for (int o = 1; o < 32; o <<= 1) {
            int u = __shfl_up_sync(0xffffffffu, incl, o);
            if (lane >= o) incl += u;
        }
        unsigned ball = __ballot_sync(0xffffffffu, incl >= k);
        int sel = __ffs(ball) - 1;
        if (lane == sel) {
            int cum = incl - sum;
            int m = -1;
            float keep = 1.0f;
#pragma unroll
            for (int j = 0; j < 8; j++) {
                int cb = v[j];
                if (m < 0 && cum + cb >= k) {
                    int gi = lane * 8 + j;
                    m = mp ? (NB - 1 - gi) : gi;
                    keep = 1.0f - (float)(k - cum) / (float)cb;
                }
                cum += cb;
            }
            g_c_keep[c] = keep;
            if (mp) g_c_m1[c] = m; else g_c_m0[c] = m;
        }
    }
}

// pass3: weighted sum + fused finalize (last block writes out)
__global__ __launch_bounds__(256) void k_pass3(const float4* __restrict__ pred,
                                               const float4* __restrict__ targ,
                                               const float4* __restrict__ rm,
                                               float* __restrict__ out,
                                               int n4, int n) {
    int tid = threadIdx.x;
    int gt = blockIdx.x * 256 + tid;
    int stride = G3 * 256;
    int c0 = (gt * 4) % NC;

    float w1[4], w0[4], dr[4], kp[4];
    int m1[4], m0[4];
#pragma unroll
    for (int j = 0; j < 4; j++) {
        int c = c0 + j;
        w1[j] = g_c_w1[c];  w0[j] = g_c_w0[c];
        dr[j] = g_c_drate[c]; kp[j] = g_c_keep[c];
        m1[j] = g_c_m1[c];  m0[j] = g_c_m0[c];
    }

    float local = 0.0f;
    for (int i = gt; i < n4; i += stride) {
        float4 x = pred[i];
        float4 t = targ[i];
        float4 r = rm[i];
        float xs[4] = {x.x, x.y, x.z, x.w};
        float ts[4] = {t.x, t.y, t.z, t.w};
        float rs[4] = {r.x, r.y, r.z, r.w};
#pragma unroll
        for (int j = 0; j < 4; j++) {
            float xv = xs[j];
            bool  t1 = ts[j] != 0.0f;
            float ax = fabsf(xv);
            float L  = __logf(1.0f + __expf(-ax));
            bool mism = (xv >= 0.0f) != t1;
            float bce = mism ? (L + ax) : L;

            int b = (int)fmaf(xv, BSC, 128.0f);
            b = min(max(b, 0), NB - 1);

            float w = t1 ? w1[j] : w0[j];
            int   m = t1 ? m1[j] : m0[j];
            if (m >= 0) {
                bool drop = t1 ? (b > m) : (b < m);
                if (drop)        w = 0.0f;
                else if (b == m) w *= kp[j];
            }
            if (mism && ax >= BANDX && rs[j] > dr[j]) w = 0.0f;
            local = fmaf(bce, w, local);
        }
    }

    // warp reduce -> block reduce -> double atomic -> last block finalizes
#pragma unroll
    for (int o = 16; o > 0; o >>= 1)
        local += __shfl_down_sync(0xffffffffu, local, o);
    __shared__ float s_red[8];
    int wid = tid >> 5, lane = tid & 31;
    if (lane == 0) s_red[wid] = local;
    __syncthreads();
    if (wid == 0) {
        float v = (lane < 8) ? s_red[lane] : 0.0f;
#pragma unroll
        for (int o = 4; o > 0; o >>= 1)
            v += __shfl_down_sync(0xffffffffu, v, o);
        if (lane == 0) {
            atomicAdd(&g_acc, (double)v);
            __threadfence();
            unsigned old = atomicAdd(&g_done, 1u);
            if (old == G3 - 1) {
                double total = atomicAdd(&g_acc, 0.0);   // coherent read
                out[0] = (float)(total / (double)n);
            }
        }
    }
}

// ---------------- launch ------------------------------------------------------
extern "C" void kernel_launch(void* const* d_in, const int* in_sizes, int n_in,
                              void* d_out, int out_size) {
    const float4* pred     = (const float4*)d_in[0];
    const float4* targ     = (const float4*)d_in[1];
    const float4* rm       = (const float4*)d_in[2];
    const float*  hard_rnd = (const float*)d_in[3];
    const float*  pos_prop = (const float*)d_in[4];
    float* out = (float*)d_out;

    int n  = in_sizes[0];           // B*C (divisible by 4)
    int n4 = n / 4;
    float Bf = (float)(n / NC);

    k_zero<<<(WORDS + 255) / 256, 256>>>();
    k_pass1<<<G1, T1>>>(pred, targ, n4);
    k_pass2<<<1, 256>>>(hard_rnd, pos_prop, Bf);
    k_pass3<<<G3, 256>>>(pred, targ, rm, out, n4, n);
}